// round 3
// baseline (speedup 1.0000x reference)
#include <cuda_runtime.h>

// CBOW negative-sampling loss.
// Shapes: context_idxs [B,CTX] i32, pos_target [B] i32, neg_samples [B,NEG] i32,
//         in_embed_W [VOCAB,DIM] f32, out_embed_W [VOCAB,DIM] f32. Output: scalar f32.
#define VOCAB 50000
#define DIM   50
#define BATCH 131072
#define CTX   10
#define NEG   10

#define THREADS     256
#define WARPS_PER_B (THREADS / 32)
#define NBLOCKS     (BATCH / WARPS_PER_B)   // 16384, one sample per warp
#define RED_THREADS 1024
#define PER_THREAD  (NBLOCKS / RED_THREADS) // 16

__device__ float g_partials[NBLOCKS];

__global__ __launch_bounds__(THREADS)
void cbow_main_kernel(const int* __restrict__ ctx,
                      const int* __restrict__ pos,
                      const int* __restrict__ neg,
                      const float* __restrict__ inW,
                      const float* __restrict__ outW)
{
    const int lane = threadIdx.x & 31;
    const int warp = threadIdx.x >> 5;
    const int b    = blockIdx.x * WARPS_PER_B + warp;   // sample id (exact cover)

    const float2* __restrict__ inW2  = (const float2*)inW;
    const float2* __restrict__ outW2 = (const float2*)outW;
    const unsigned FULL = 0xffffffffu;
    const bool act = (lane < 25);           // 25 lanes x float2 = 50 dims

    // Gather indices: lanes 0..9 hold one ctx / one neg index each; broadcast via shfl.
    int ctx_i = 0, neg_i = 0;
    if (lane < CTX) ctx_i = __ldg(&ctx[b * CTX + lane]);
    if (lane < NEG) neg_i = __ldg(&neg[b * NEG + lane]);
    const int pos_i = __ldg(&pos[b]);       // same addr across warp -> 1 request

    // ---- context vector: mean of CTX in_embed rows (front-batched loads) ----
    float2 ce[CTX];
    #pragma unroll
    for (int c = 0; c < CTX; c++) {
        int r = __shfl_sync(FULL, ctx_i, c);
        ce[c] = act ? __ldg(&inW2[r * 25 + lane]) : make_float2(0.f, 0.f);
    }
    float2 cv = make_float2(0.f, 0.f);
    #pragma unroll
    for (int c = 0; c < CTX; c++) { cv.x += ce[c].x; cv.y += ce[c].y; }
    cv.x *= (1.0f / CTX);
    cv.y *= (1.0f / CTX);

    // ---- 11 out_embed rows: pos + NEG negs (front-batched) ----
    float2 oe[NEG + 1];
    oe[0] = act ? __ldg(&outW2[pos_i * 25 + lane]) : make_float2(0.f, 0.f);
    #pragma unroll
    for (int k = 0; k < NEG; k++) {
        int r = __shfl_sync(FULL, neg_i, k);
        oe[k + 1] = act ? __ldg(&outW2[r * 25 + lane]) : make_float2(0.f, 0.f);
    }

    // Per-lane partial dots (inactive lanes contribute exact 0).
    float p[NEG + 1];
    #pragma unroll
    for (int j = 0; j <= NEG; j++)
        p[j] = cv.x * oe[j].x + cv.y * oe[j].y;

    // Batched butterfly reduction: 11 independent chains, fully pipelined.
    #pragma unroll
    for (int o = 16; o > 0; o >>= 1) {
        #pragma unroll
        for (int j = 0; j <= NEG; j++)
            p[j] += __shfl_xor_sync(FULL, p[j], o);
    }

    // loss = log(sigmoid(pos)+eps) + sum_k log(sigmoid(-neg_k)+eps)
    float loss = __logf(1.0f / (1.0f + __expf(-p[0])) + 1e-10f);
    #pragma unroll
    for (int k = 1; k <= NEG; k++)
        loss += __logf(1.0f / (1.0f + __expf(p[k])) + 1e-10f);

    // ---- deterministic block partial ----
    __shared__ float smem[WARPS_PER_B];
    if (lane == 0) smem[warp] = loss;
    __syncthreads();
    if (threadIdx.x == 0) {
        float t = 0.f;
        #pragma unroll
        for (int i = 0; i < WARPS_PER_B; i++) t += smem[i];
        g_partials[blockIdx.x] = t;
    }
}

__global__ __launch_bounds__(RED_THREADS)
void cbow_reduce_kernel(float* __restrict__ out)
{
    __shared__ float sh[RED_THREADS];
    const int tid = threadIdx.x;
    float t = 0.f;
    #pragma unroll
    for (int i = 0; i < PER_THREAD; i++)
        t += g_partials[tid + i * RED_THREADS];
    sh[tid] = t;
    __syncthreads();
    #pragma unroll
    for (int s = RED_THREADS / 2; s > 0; s >>= 1) {
        if (tid < s) sh[tid] += sh[tid + s];
        __syncthreads();
    }
    if (tid == 0) out[0] = -sh[0] / (float)BATCH;
}

extern "C" void kernel_launch(void* const* d_in, const int* in_sizes, int n_in,
                              void* d_out, int out_size)
{
    const int*   ctx  = (const int*)d_in[0];   // [B, CTX]
    const int*   pos  = (const int*)d_in[1];   // [B]
    const int*   neg  = (const int*)d_in[2];   // [B, NEG]
    const float* inW  = (const float*)d_in[3]; // [VOCAB, DIM]
    const float* outW = (const float*)d_in[4]; // [VOCAB, DIM]
    float* out = (float*)d_out;

    cbow_main_kernel<<<NBLOCKS, THREADS>>>(ctx, pos, neg, inW, outW);
    cbow_reduce_kernel<<<1, RED_THREADS>>>(out);
}

// round 4
// speedup vs baseline: 1.7481x; 1.7481x over previous
#include <cuda_runtime.h>

// CBOW negative-sampling loss, round 4.
// ctx [B,CTX] i32, pos [B] i32, neg [B,NEG] i32, inW [V,D] f32, outW [V,D] f32 -> scalar f32.
#define VOCAB 50000
#define DIM   50
#define BATCH 131072
#define CTX   10
#define NEG   10

#define THREADS 512
#define WPB     (THREADS / 32)      // 16 warps = 16 samples per block
#define NBLOCKS (BATCH / WPB)       // 8192
#define RED_T   1024

#define RSTRIDE 28                  // padded row stride (floats) for the transpose buffer

__device__ __align__(16) float g_partials[NBLOCKS];

__global__ __launch_bounds__(THREADS)
void cbow_main(const int* __restrict__ ctx,
               const int* __restrict__ pos,
               const int* __restrict__ neg,
               const float* __restrict__ inW,
               const float* __restrict__ outW)
{
    __shared__ int s_ctx[WPB * CTX];
    __shared__ int s_neg[WPB * NEG];
    __shared__ int s_pos[WPB];
    __shared__ __align__(16) float s_red[WPB][11 * RSTRIDE]; // [11][25] padded per warp
    __shared__ float s_wl[WPB];

    const int tid  = threadIdx.x;
    const int lane = tid & 31;
    const int warp = tid >> 5;
    const int B0   = blockIdx.x * WPB;
    const unsigned FULL = 0xffffffffu;

    // ---- stage this block's indices once, coalesced ----
    if (tid < WPB * CTX) s_ctx[tid] = __ldg(&ctx[B0 * CTX + tid]);
    if (tid < WPB * NEG) s_neg[tid] = __ldg(&neg[B0 * NEG + tid]);
    if (tid < WPB)       s_pos[tid] = __ldg(&pos[B0 + tid]);
    __syncthreads();

    const float2* __restrict__ inW2  = (const float2*)inW;
    const float2* __restrict__ outW2 = (const float2*)outW;
    const bool act = (lane < 25);   // 25 lanes x float2 = 50 dims

    // ---- front-batched gathers: 21 independent LDG.64 in flight ----
    float2 ce[CTX];
    #pragma unroll
    for (int c = 0; c < CTX; c++) {
        int r = s_ctx[warp * CTX + c];                 // uniform broadcast LDS
        ce[c] = act ? __ldg(&inW2[r * 25 + lane]) : make_float2(0.f, 0.f);
    }
    float2 oe[NEG + 1];
    {
        int r = s_pos[warp];
        oe[0] = act ? __ldg(&outW2[r * 25 + lane]) : make_float2(0.f, 0.f);
    }
    #pragma unroll
    for (int k = 0; k < NEG; k++) {
        int r = s_neg[warp * NEG + k];
        oe[k + 1] = act ? __ldg(&outW2[r * 25 + lane]) : make_float2(0.f, 0.f);
    }

    // ---- context mean (elementwise, pairwise-ish tree) ----
    float2 cv = make_float2(0.f, 0.f);
    #pragma unroll
    for (int c = 0; c < CTX; c++) { cv.x += ce[c].x; cv.y += ce[c].y; }
    cv.x *= (1.0f / CTX);
    cv.y *= (1.0f / CTX);

    // ---- per-lane partial dots for the 11 targets ----
    float p[NEG + 1];
    #pragma unroll
    for (int j = 0; j <= NEG; j++)
        p[j] = cv.x * oe[j].x + cv.y * oe[j].y;

    // ---- transpose via smem: lane j ends up owning dot j (no butterfly) ----
    if (act) {
        #pragma unroll
        for (int j = 0; j <= NEG; j++)
            s_red[warp][j * RSTRIDE + lane] = p[j];    // 25 lanes, conflict-free
    }
    __syncwarp();

    float term = 0.f;
    if (lane <= NEG) {
        const float* row = &s_red[warp][lane * RSTRIDE];
        float4 a = *(const float4*)(row);
        float4 b = *(const float4*)(row + 4);
        float4 c = *(const float4*)(row + 8);
        float4 d = *(const float4*)(row + 12);
        float4 e = *(const float4*)(row + 16);
        float4 f = *(const float4*)(row + 20);
        float s = ((a.x + a.y) + (a.z + a.w)) + ((b.x + b.y) + (b.z + b.w))
                + ((c.x + c.y) + (c.z + c.w)) + ((d.x + d.y) + (d.z + d.w))
                + ((e.x + e.y) + (e.z + e.w)) + ((f.x + f.y) + (f.z + f.w))
                + row[24];
        // lane 0: log(sigmoid(pos_score)+eps); lanes 1..10: log(sigmoid(-neg_score)+eps)
        float arg = (lane == 0) ? s : -s;
        float sg  = 1.0f / (1.0f + __expf(-arg));
        term = __logf(sg + 1e-10f);                    // 3 MUFU total, lane-parallel
    }
    // sum lanes 0..15 (11..15 carry zero) — 4 SHFLs
    #pragma unroll
    for (int o = 8; o > 0; o >>= 1)
        term += __shfl_xor_sync(FULL, term, o);

    if (lane == 0) s_wl[warp] = term;
    __syncthreads();
    if (tid == 0) {
        float t = 0.f;
        #pragma unroll
        for (int i = 0; i < WPB; i++) t += s_wl[i];
        g_partials[blockIdx.x] = t;
    }
}

__global__ __launch_bounds__(RED_T)
void cbow_reduce(float* __restrict__ out)
{
    const float4* __restrict__ p4 = (const float4*)g_partials;  // 2048 float4
    const int tid  = threadIdx.x;
    const int lane = tid & 31;
    const int warp = tid >> 5;
    const unsigned FULL = 0xffffffffu;

    float4 a = p4[tid];
    float4 b = p4[tid + RED_T];
    float t = ((a.x + a.y) + (a.z + a.w)) + ((b.x + b.y) + (b.z + b.w));

    #pragma unroll
    for (int o = 16; o > 0; o >>= 1)
        t += __shfl_xor_sync(FULL, t, o);

    __shared__ float s[32];
    if (lane == 0) s[warp] = t;
    __syncthreads();
    if (tid < 32) {
        float v = s[tid];
        #pragma unroll
        for (int o = 16; o > 0; o >>= 1)
            v += __shfl_xor_sync(FULL, v, o);
        if (tid == 0) out[0] = -v / (float)BATCH;
    }
}

extern "C" void kernel_launch(void* const* d_in, const int* in_sizes, int n_in,
                              void* d_out, int out_size)
{
    const int*   ctx  = (const int*)d_in[0];   // [B, CTX]
    const int*   pos  = (const int*)d_in[1];   // [B]
    const int*   neg  = (const int*)d_in[2];   // [B, NEG]
    const float* inW  = (const float*)d_in[3]; // [VOCAB, DIM]
    const float* outW = (const float*)d_in[4]; // [VOCAB, DIM]
    float* out = (float*)d_out;

    cbow_main<<<NBLOCKS, THREADS>>>(ctx, pos, neg, inW, outW);
    cbow_reduce<<<1, RED_T>>>(out);
}

// round 5
// speedup vs baseline: 1.9230x; 1.1000x over previous
#include <cuda_runtime.h>

// CBOW negative-sampling loss, round 5.
// ctx [B,CTX] i32, pos [B] i32, neg [B,NEG] i32, inW [V,D] f32, outW [V,D] f32 -> scalar f32.
#define VOCAB 50000
#define DIM   50
#define BATCH 131072
#define CTX   10
#define NEG   10

#define THREADS  256
#define WPB      (THREADS / 32)          // 8 samples per block
#define NBLOCKS  (BATCH / WPB)           // 16384
#define RED_B    128
#define RED_T    1024                    // 128*1024 = 131072 exact

#define RSTRIDE  28                      // 28 floats = 112B (16B-aligned rows)

__device__ __align__(16) float    g_wl[BATCH];   // per-sample loss
__device__ __align__(16) float    g_red[RED_B];  // per-block partials of reduce
__device__ unsigned               g_cnt = 0;     // last-block counter (self-resetting)

__global__ __launch_bounds__(THREADS, 4)
void cbow_main(const int* __restrict__ ctx,
               const int* __restrict__ pos,
               const int* __restrict__ neg,
               const float* __restrict__ inW,
               const float* __restrict__ outW)
{
    __shared__ int s_ctx[WPB * CTX];
    __shared__ int s_neg[WPB * NEG];
    __shared__ int s_pos[WPB];
    __shared__ __align__(16) float s_red[WPB][11 * RSTRIDE];

    const int tid  = threadIdx.x;
    const int lane = tid & 31;
    const int warp = tid >> 5;
    const int B0   = blockIdx.x * WPB;
    const unsigned FULL = 0xffffffffu;

    // ---- stage this block's 168 indices, coalesced ----
    if (tid < WPB * CTX) s_ctx[tid] = __ldg(&ctx[B0 * CTX + tid]);
    if (tid < WPB * NEG) s_neg[tid] = __ldg(&neg[B0 * NEG + tid]);
    if (tid < WPB)       s_pos[tid] = __ldg(&pos[B0 + tid]);
    __syncthreads();

    const float2* __restrict__ inW2  = (const float2*)inW;
    const float2* __restrict__ outW2 = (const float2*)outW;
    const bool act = (lane < 25);            // 25 lanes x float2 = 50 dims

    // ---- phase 1: CTX gathers (10 in flight), then fold to context mean ----
    float2 ce[CTX];
    #pragma unroll
    for (int c = 0; c < CTX; c++) {
        int r = s_ctx[warp * CTX + c];
        ce[c] = act ? __ldg(&inW2[r * 25 + lane]) : make_float2(0.f, 0.f);
    }
    float2 cv = make_float2(0.f, 0.f);
    #pragma unroll
    for (int c = 0; c < CTX; c++) { cv.x += ce[c].x; cv.y += ce[c].y; }
    cv.x *= (1.0f / CTX);
    cv.y *= (1.0f / CTX);

    // ---- phase 2: 11 out_embed gathers (11 in flight) ----
    float2 oe[NEG + 1];
    {
        int r = s_pos[warp];
        oe[0] = act ? __ldg(&outW2[r * 25 + lane]) : make_float2(0.f, 0.f);
    }
    #pragma unroll
    for (int k = 0; k < NEG; k++) {
        int r = s_neg[warp * NEG + k];
        oe[k + 1] = act ? __ldg(&outW2[r * 25 + lane]) : make_float2(0.f, 0.f);
    }

    // ---- per-lane partial dots ----
    float p[NEG + 1];
    #pragma unroll
    for (int j = 0; j <= NEG; j++)
        p[j] = cv.x * oe[j].x + cv.y * oe[j].y;

    // ---- smem transpose: lane j owns dot j ----
    if (act) {
        #pragma unroll
        for (int j = 0; j <= NEG; j++)
            s_red[warp][j * RSTRIDE + lane] = p[j];
    }
    __syncwarp();

    float term = 0.f;
    if (lane <= NEG) {
        const float* row = &s_red[warp][lane * RSTRIDE];
        float4 a = *(const float4*)(row);
        float4 b = *(const float4*)(row + 4);
        float4 c = *(const float4*)(row + 8);
        float4 d = *(const float4*)(row + 12);
        float4 e = *(const float4*)(row + 16);
        float4 f = *(const float4*)(row + 20);
        float s = ((a.x + a.y) + (a.z + a.w)) + ((b.x + b.y) + (b.z + b.w))
                + ((c.x + c.y) + (c.z + c.w)) + ((d.x + d.y) + (d.z + d.w))
                + ((e.x + e.y) + (e.z + e.w)) + ((f.x + f.y) + (f.z + f.w))
                + row[24];
        float arg = (lane == 0) ? s : -s;    // pos uses +score, negs use -score
        float sg  = 1.0f / (1.0f + __expf(-arg));
        term = __logf(sg + 1e-10f);
    }
    #pragma unroll
    for (int o = 8; o > 0; o >>= 1)          // sum lanes 0..15 (11..15 are zero)
        term += __shfl_xor_sync(FULL, term, o);

    // warp-granular retirement: no trailing block sync, no tid0 serialization
    if (lane == 0) g_wl[B0 + warp] = term;
}

__global__ __launch_bounds__(RED_T)
void cbow_reduce(float* __restrict__ out)
{
    __shared__ float s[32];
    __shared__ bool  isLast;
    const int tid  = threadIdx.x;
    const int lane = tid & 31;
    const int warp = tid >> 5;
    const unsigned FULL = 0xffffffffu;

    float t = g_wl[blockIdx.x * RED_T + tid];
    #pragma unroll
    for (int o = 16; o > 0; o >>= 1)
        t += __shfl_xor_sync(FULL, t, o);
    if (lane == 0) s[warp] = t;
    __syncthreads();
    if (tid < 32) {
        float v = s[tid];
        #pragma unroll
        for (int o = 16; o > 0; o >>= 1)
            v += __shfl_xor_sync(FULL, v, o);
        if (tid == 0) {
            g_red[blockIdx.x] = v;
            __threadfence();
            unsigned old = atomicAdd(&g_cnt, 1u);
            isLast = (old == RED_B - 1);
        }
    }
    __syncthreads();

    if (isLast && tid < 32) {                 // deterministic fixed-order final sum
        float v = __ldcg(&g_red[tid])      + __ldcg(&g_red[tid + 32])
                + __ldcg(&g_red[tid + 64]) + __ldcg(&g_red[tid + 96]);
        #pragma unroll
        for (int o = 16; o > 0; o >>= 1)
            v += __shfl_xor_sync(FULL, v, o);
        if (tid == 0) {
            out[0] = -v / (float)BATCH;
            g_cnt = 0;                        // reset for next graph replay
        }
    }
}

extern "C" void kernel_launch(void* const* d_in, const int* in_sizes, int n_in,
                              void* d_out, int out_size)
{
    const int*   ctx  = (const int*)d_in[0];   // [B, CTX]
    const int*   pos  = (const int*)d_in[1];   // [B]
    const int*   neg  = (const int*)d_in[2];   // [B, NEG]
    const float* inW  = (const float*)d_in[3]; // [VOCAB, DIM]
    const float* outW = (const float*)d_in[4]; // [VOCAB, DIM]
    float* out = (float*)d_out;

    cbow_main<<<NBLOCKS, THREADS>>>(ctx, pos, neg, inW, outW);
    cbow_reduce<<<RED_B, RED_T>>>(out);
}